// round 7
// baseline (speedup 1.0000x reference)
#include <cuda_runtime.h>
#include <math.h>
#include <stdint.h>

#define N_NODES 8192
#define F_IN    512
#define F_OUT   64
#define ALPHA   0.2f

#define TJ      32
#define JSPLIT  16
#define JQ      (N_NODES / JSPLIT)   // 512
#define TILES_B (JQ / TJ)            // 16 tiles per block
#define ROWS_B  64                   // i-rows per block

// SMEM stage layout (bytes)
#define ADJ_STRIDE 144               // 36 ints per adj row (32 data + pad)
#define WH_STRIDE  288               // 72 floats per Wh row (64 data + pad)
#define WH_OFF     9216              // after 64 adj rows
#define S2_OFF     18432
#define STAGE      18560
#define RING       4
#define SMEM_SZ    (STAGE * RING)    // 74240 (x3 blocks = 222.7KB/SM)

// Scratch (no allocations allowed anywhere)
__device__ float g_Wh [N_NODES * F_OUT];
__device__ float g_WhB[N_NODES * F_OUT];   // tf32-rounded, COLUMN-PERMUTED: p(f)=(f&7)*8+(f>>3)
__device__ float g_s1 [N_NODES];
__device__ float g_s2 [N_NODES];
__device__ float g_s2max;
__device__ float g_part [JSPLIT][N_NODES * F_OUT];
__device__ float g_lpart[JSPLIT][N_NODES];

// ---- helpers ---------------------------------------------------------------
__device__ __forceinline__ uint32_t smem_u32(const void* p) {
    uint32_t r;
    asm("{ .reg .u64 t; cvta.to.shared.u64 t, %1; cvt.u32.u64 %0, t; }"
        : "=r"(r) : "l"(p));
    return r;
}
__device__ __forceinline__ void cp_async16(uint32_t dst, const void* src) {
    asm volatile("cp.async.cg.shared.global [%0], [%1], 16;"
                 :: "r"(dst), "l"(src) : "memory");
}
__device__ __forceinline__ void cp_commit() {
    asm volatile("cp.async.commit_group;" ::: "memory");
}
__device__ __forceinline__ void cp_wait1() {
    asm volatile("cp.async.wait_group 1;" ::: "memory");
}
__device__ __forceinline__ void cp_wait2() {
    asm volatile("cp.async.wait_group 2;" ::: "memory");
}
__device__ __forceinline__ uint32_t to_tf32(float x) {
    uint32_t r;
    asm("cvt.rna.tf32.f32 %0, %1;" : "=r"(r) : "f"(x));
    return r;
}
__device__ __forceinline__ void mma_tf32(float* c, uint32_t a0, uint32_t a1,
                                         uint32_t a2, uint32_t a3,
                                         uint32_t b0, uint32_t b1) {
    asm volatile(
        "mma.sync.aligned.m16n8k8.row.col.f32.tf32.tf32.f32 "
        "{%0,%1,%2,%3}, {%4,%5,%6,%7}, {%8,%9}, {%0,%1,%2,%3};"
        : "+f"(c[0]), "+f"(c[1]), "+f"(c[2]), "+f"(c[3])
        : "r"(a0), "r"(a1), "r"(a2), "r"(a3), "r"(b0), "r"(b1));
}

// ---------------------------------------------------------------------------
// Kernel A: Wh = x @ W via tf32 mma.sync. Block = 64 rows x 64 cols, K=512.
// Writes g_Wh (natural layout, fp32) and g_WhB (tf32, column-permuted).
// ---------------------------------------------------------------------------
#define XS_STR 36
#define WS_STR 72
__global__ __launch_bounds__(256) void wh_kernel(const float* __restrict__ x,
                                                 const float* __restrict__ W) {
    __shared__ __align__(16) float xs[2][64 * XS_STR];
    __shared__ __align__(16) float ws[2][32 * WS_STR];

    const int tid  = threadIdx.x;
    const int w    = tid >> 5, lane = tid & 31;
    const int wr   = w & 3,    wc   = w >> 2;
    const int g    = lane >> 2, tig = lane & 3;
    const int r0   = blockIdx.x * 64;
    const int r0l  = wr * 16 + g;
    const int r1l  = r0l + 8;

    const uint32_t xs0 = smem_u32(xs);
    const uint32_t ws0 = smem_u32(ws);

    auto prefetch = [&](int s) {
        if (s < 16) {
            int b = s & 1;
            int k0 = s * 32;
            #pragma unroll
            for (int c = tid; c < 512; c += 256) {     // x: 64 rows x 32 k
                int r = c >> 3, q = c & 7;
                cp_async16(xs0 + (b * 64 * XS_STR + r * XS_STR) * 4 + q * 16,
                           x + (size_t)(r0 + r) * F_IN + k0 + q * 4);
            }
            #pragma unroll
            for (int c = tid; c < 512; c += 256) {     // W: 32 k x 64 f
                int r = c >> 4, q = c & 15;
                cp_async16(ws0 + (b * 32 * WS_STR + r * WS_STR) * 4 + q * 16,
                           W + (size_t)(k0 + r) * F_OUT + q * 4);
            }
        }
        cp_commit();
    };

    float acc[4][4] = {};
    prefetch(0);

    for (int s = 0; s < 16; ++s) {
        prefetch(s + 1);
        cp_wait1();
        __syncthreads();

        const float* xp = &xs[s & 1][0];
        const float* wp = &ws[s & 1][0];

        #pragma unroll
        for (int kc = 0; kc < 4; ++kc) {
            uint32_t a0 = to_tf32(xp[r0l * XS_STR + kc * 8 + tig]);
            uint32_t a1 = to_tf32(xp[r1l * XS_STR + kc * 8 + tig]);
            uint32_t a2 = to_tf32(xp[r0l * XS_STR + kc * 8 + tig + 4]);
            uint32_t a3 = to_tf32(xp[r1l * XS_STR + kc * 8 + tig + 4]);
            #pragma unroll
            for (int n = 0; n < 4; ++n) {
                int f = wc * 32 + n * 8 + g;
                uint32_t b0 = to_tf32(wp[(kc * 8 + tig)     * WS_STR + f]);
                uint32_t b1 = to_tf32(wp[(kc * 8 + tig + 4) * WS_STR + f]);
                mma_tf32(acc[n], a0, a1, a2, a3, b0, b1);
            }
        }
        __syncthreads();
    }

    #pragma unroll
    for (int n = 0; n < 4; ++n) {
        int f = wc * 32 + n * 8 + tig * 2;   // original columns f, f+1
        size_t o0 = (size_t)(r0 + r0l) * F_OUT + f;
        size_t o1 = (size_t)(r0 + r1l) * F_OUT + f;
        *(float2*)&g_Wh[o0] = make_float2(acc[n][0], acc[n][1]);
        *(float2*)&g_Wh[o1] = make_float2(acc[n][2], acc[n][3]);
        // permuted positions: p(f) = tig*16 + wc*4 + n ; p(f+1) = p(f)+8
        int p0 = tig * 16 + wc * 4 + n;
        g_WhB[(size_t)(r0 + r0l) * F_OUT + p0]     = __uint_as_float(to_tf32(acc[n][0]));
        g_WhB[(size_t)(r0 + r0l) * F_OUT + p0 + 8] = __uint_as_float(to_tf32(acc[n][1]));
        g_WhB[(size_t)(r0 + r1l) * F_OUT + p0]     = __uint_as_float(to_tf32(acc[n][2]));
        g_WhB[(size_t)(r0 + r1l) * F_OUT + p0 + 8] = __uint_as_float(to_tf32(acc[n][3]));
    }
}

// ---------------------------------------------------------------------------
// Kernel B: s1 = Wh @ a1, s2 = Wh @ a2
// ---------------------------------------------------------------------------
__global__ __launch_bounds__(256) void s_kernel(const float* __restrict__ A) {
    const int row  = blockIdx.x * 8 + (threadIdx.x >> 5);
    const int lane = threadIdx.x & 31;
    float w0 = g_Wh[row * F_OUT + lane];
    float w1 = g_Wh[row * F_OUT + lane + 32];
    float v1 = w0 * A[lane]         + w1 * A[lane + 32];
    float v2 = w0 * A[F_OUT + lane] + w1 * A[F_OUT + lane + 32];
    #pragma unroll
    for (int off = 16; off; off >>= 1) {
        v1 += __shfl_xor_sync(0xFFFFFFFFu, v1, off);
        v2 += __shfl_xor_sync(0xFFFFFFFFu, v2, off);
    }
    if (lane == 0) { g_s1[row] = v1; g_s2[row] = v2; }
}

// ---------------------------------------------------------------------------
// Kernel B2: g_s2max = max(g_s2)
// ---------------------------------------------------------------------------
__global__ __launch_bounds__(1024) void s2max_kernel() {
    __shared__ float sm[32];
    const int tid = threadIdx.x;
    float m = -INFINITY;
    for (int i = tid; i < N_NODES; i += 1024) m = fmaxf(m, g_s2[i]);
    #pragma unroll
    for (int off = 16; off; off >>= 1)
        m = fmaxf(m, __shfl_xor_sync(0xFFFFFFFFu, m, off));
    if ((tid & 31) == 0) sm[tid >> 5] = m;
    __syncthreads();
    if (tid < 32) {
        m = sm[tid];
        #pragma unroll
        for (int off = 16; off; off >>= 1)
            m = fmaxf(m, __shfl_xor_sync(0xFFFFFFFFu, m, off));
        if (tid == 0) g_s2max = m;
    }
}

// ---------------------------------------------------------------------------
// Kernel C: fused attention via mma.sync tf32 (m16n8k8).
// grid = 128 i-blocks x 16 j-slices = 2048 blocks, 3 blocks/SM.
// B fragments from permuted WhB: 4 n-values contiguous -> LDS.128.
// ---------------------------------------------------------------------------
__global__ __launch_bounds__(256, 3) void attn_kernel(const int* __restrict__ adj) {
    extern __shared__ __align__(1024) char smem[];
    const int tid  = threadIdx.x;
    const int w    = tid >> 5, lane = tid & 31;
    const int wr   = w & 3,    wc   = w >> 2;
    const int g    = lane >> 2, tig = lane & 3;
    const int i0   = (blockIdx.x >> 4) * ROWS_B;
    const int qh   = blockIdx.x & 15;
    const int j0b  = qh * JQ;
    const int r0l  = wr * 16 + g;
    const int r1l  = r0l + 8;

    const uint32_t sb = smem_u32(smem);

    auto prefetch = [&](int t) {
        if (t < TILES_B) {
            uint32_t base = sb + (t & 3) * STAGE;
            const int j0 = j0b + t * TJ;
            #pragma unroll
            for (int c = tid; c < 512; c += 256) {       // adj 64x32 ints
                int r = c >> 3, q = c & 7;
                cp_async16(base + r * ADJ_STRIDE + q * 16,
                           adj + (size_t)(i0 + r) * N_NODES + j0 + q * 4);
            }
            #pragma unroll
            for (int c = tid; c < 512; c += 256) {       // WhB 32x64 floats
                int r = c >> 4, q = c & 15;
                cp_async16(base + WH_OFF + r * WH_STRIDE + q * 16,
                           g_WhB + (j0 + r) * F_OUT + q * 4);
            }
            if (tid < 8)                                 // s2 32 floats
                cp_async16(base + S2_OFF + tid * 16, g_s2 + j0 + tid * 4);
        }
        cp_commit();
    };

    const float s1_0 = g_s1[i0 + r0l];
    const float s1_1 = g_s1[i0 + r1l];
    const float s2m  = g_s2max;
    const float m0 = fmaxf(s1_0 + s2m, ALPHA * (s1_0 + s2m));
    const float m1 = fmaxf(s1_1 + s2m, ALPHA * (s1_1 + s2m));

    float acc[4][4] = {};
    float sum0 = 0.f, sum1 = 0.f;

    prefetch(0); prefetch(1); prefetch(2);

    for (int t = 0; t < TILES_B; ++t) {
        cp_wait2();
        __syncthreads();
        prefetch(t + 3);     // refills slot (t-1)&3; reads of t-1 done pre-barrier

        const char*  base = smem + (t & 3) * STAGE;
        const float* s2p  = (const float*)(base + S2_OFF);
        const float* whp  = (const float*)(base + WH_OFF);

        // A fragments: 16 weights (2 rows x 8 j-cols), rounded to tf32
        uint32_t aw0[8], aw1[8];
        #pragma unroll
        for (int mm = 0; mm < 8; ++mm) {
            int j = tig + 4 * mm;
            float s2v = s2p[j];
            int a0 = *(const int*)(base + r0l * ADJ_STRIDE + j * 4);
            int a1 = *(const int*)(base + r1l * ADJ_STRIDE + j * 4);
            float t0 = s1_0 + s2v;
            float t1 = s1_1 + s2v;
            float e0 = fmaxf(t0, ALPHA * t0);
            float e1 = fmaxf(t1, ALPHA * t1);
            float w0 = (a0 > 0) ? __expf(e0 - m0) : 0.f;
            float w1 = (a1 > 0) ? __expf(e1 - m1) : 0.f;
            sum0 += w0; sum1 += w1;
            aw0[mm] = to_tf32(w0);
            aw1[mm] = to_tf32(w1);
        }

        // B fragments via LDS.128 (permuted layout: n=0..3 contiguous)
        #pragma unroll
        for (int k = 0; k < 4; ++k) {
            float4 bv0 = *(const float4*)&whp[(k * 8 + tig)     * 72 + g * 8 + wc * 4];
            float4 bv1 = *(const float4*)&whp[(k * 8 + tig + 4) * 72 + g * 8 + wc * 4];
            uint32_t a0 = aw0[2 * k],     a1 = aw1[2 * k];
            uint32_t a2 = aw0[2 * k + 1], a3 = aw1[2 * k + 1];
            mma_tf32(acc[0], a0, a1, a2, a3,
                     __float_as_uint(bv0.x), __float_as_uint(bv1.x));
            mma_tf32(acc[1], a0, a1, a2, a3,
                     __float_as_uint(bv0.y), __float_as_uint(bv1.y));
            mma_tf32(acc[2], a0, a1, a2, a3,
                     __float_as_uint(bv0.z), __float_as_uint(bv1.z));
            mma_tf32(acc[3], a0, a1, a2, a3,
                     __float_as_uint(bv0.w), __float_as_uint(bv1.w));
        }
    }

    // partial row sums (wc==0 warps own them; wc==1 computed duplicates)
    if (wc == 0) {
        sum0 += __shfl_xor_sync(0xFFFFFFFFu, sum0, 1);
        sum0 += __shfl_xor_sync(0xFFFFFFFFu, sum0, 2);
        sum1 += __shfl_xor_sync(0xFFFFFFFFu, sum1, 1);
        sum1 += __shfl_xor_sync(0xFFFFFFFFu, sum1, 2);
        if (tig == 0) {
            g_lpart[qh][i0 + r0l] = sum0;
            g_lpart[qh][i0 + r1l] = sum1;
        }
    }

    // unnormalized partial outputs (original column order)
    #pragma unroll
    for (int n = 0; n < 4; ++n) {
        int f = wc * 32 + n * 8 + tig * 2;
        *(float2*)&g_part[qh][(size_t)(i0 + r0l) * F_OUT + f] =
            make_float2(acc[n][0], acc[n][1]);
        *(float2*)&g_part[qh][(size_t)(i0 + r1l) * F_OUT + f] =
            make_float2(acc[n][2], acc[n][3]);
    }
}

// ---------------------------------------------------------------------------
// Kernel D: out = (sum_q part_q) / (sum_q l_q) + bias
// ---------------------------------------------------------------------------
__global__ __launch_bounds__(256) void combine_kernel(const float* __restrict__ bias,
                                                      float* __restrict__ out) {
    int idx = blockIdx.x * 256 + threadIdx.x;    // 8192*16 float4 slots
    int i  = idx >> 4;
    int fq = idx & 15;
    size_t off = (size_t)i * F_OUT + fq * 4;

    float4 p = *(const float4*)&g_part[0][off];
    float  l = g_lpart[0][i];
    #pragma unroll
    for (int q = 1; q < JSPLIT; ++q) {
        float4 pq = *(const float4*)&g_part[q][off];
        p.x += pq.x; p.y += pq.y; p.z += pq.z; p.w += pq.w;
        l += g_lpart[q][i];
    }
    float inv = 1.0f / l;
    float4 bz = *(const float4*)&bias[fq * 4];
    float4 r;
    r.x = p.x * inv + bz.x;
    r.y = p.y * inv + bz.y;
    r.z = p.z * inv + bz.z;
    r.w = p.w * inv + bz.w;
    *(float4*)&out[off] = r;
}

// ---------------------------------------------------------------------------
extern "C" void kernel_launch(void* const* d_in, const int* in_sizes, int n_in,
                              void* d_out, int out_size) {
    const float* x    = (const float*)d_in[0];
    const int*   adj  = (const int*)  d_in[1];
    const float* W    = (const float*)d_in[2];
    const float* bias = (const float*)d_in[3];
    const float* A    = (const float*)d_in[4];
    float*       out  = (float*)d_out;

    cudaFuncSetAttribute(attn_kernel,
                         cudaFuncAttributeMaxDynamicSharedMemorySize, SMEM_SZ);

    wh_kernel   <<<N_NODES / 64, 256>>>(x, W);
    s_kernel    <<<N_NODES / 8,  256>>>(A);
    s2max_kernel<<<1, 1024>>>();
    attn_kernel <<<(N_NODES / ROWS_B) * JSPLIT, 256, SMEM_SZ>>>(adj);
    combine_kernel<<<N_NODES * 16 / 256, 256>>>(bias, out);
}

// round 8
// speedup vs baseline: 1.3577x; 1.3577x over previous
#include <cuda_runtime.h>
#include <math.h>
#include <stdint.h>

#define N_NODES 8192
#define F_IN    512
#define F_OUT   64
#define ALPHA   0.2f

#define TJ      32
#define JSPLIT  8
#define JQ      (N_NODES / JSPLIT)   // 1024
#define TILES_B (JQ / TJ)            // 32 tiles per block
#define ROWS_B  64                   // i-rows per block

// SMEM stage layout (bytes)
#define ADJ_STRIDE 144               // 36 ints per adj row (32 data + pad)
#define WH_STRIDE  288               // 72 floats per Wh row (64 data + pad)
#define WH_OFF     9216              // after 64 adj rows
#define S2_OFF     18432
#define STAGE      18560
#define RING       4
#define SMEM_SZ    (STAGE * RING)    // 74240 (x3 blocks = 222.7KB/SM)

// Scratch (no allocations allowed anywhere)
__device__ float g_Wh [N_NODES * F_OUT];
// tf32-rounded, column-permuted: p(f) = (n>>2)*32 + (f&7)*4 + (n&3), n = f>>3
__device__ float g_WhB[N_NODES * F_OUT];
__device__ float g_s1 [N_NODES];
__device__ float g_s2 [N_NODES];
__device__ float g_s2max;
__device__ float g_part [JSPLIT][N_NODES * F_OUT];
__device__ float g_lpart[JSPLIT][N_NODES];

// ---- helpers ---------------------------------------------------------------
__device__ __forceinline__ uint32_t smem_u32(const void* p) {
    uint32_t r;
    asm("{ .reg .u64 t; cvta.to.shared.u64 t, %1; cvt.u32.u64 %0, t; }"
        : "=r"(r) : "l"(p));
    return r;
}
__device__ __forceinline__ void cp_async16(uint32_t dst, const void* src) {
    asm volatile("cp.async.cg.shared.global [%0], [%1], 16;"
                 :: "r"(dst), "l"(src) : "memory");
}
__device__ __forceinline__ void cp_commit() {
    asm volatile("cp.async.commit_group;" ::: "memory");
}
__device__ __forceinline__ void cp_wait1() {
    asm volatile("cp.async.wait_group 1;" ::: "memory");
}
__device__ __forceinline__ void cp_wait2() {
    asm volatile("cp.async.wait_group 2;" ::: "memory");
}
__device__ __forceinline__ uint32_t to_tf32(float x) {
    uint32_t r;
    asm("cvt.rna.tf32.f32 %0, %1;" : "=r"(r) : "f"(x));
    return r;
}
__device__ __forceinline__ void mma_tf32(float* c, uint32_t a0, uint32_t a1,
                                         uint32_t a2, uint32_t a3,
                                         uint32_t b0, uint32_t b1) {
    asm volatile(
        "mma.sync.aligned.m16n8k8.row.col.f32.tf32.tf32.f32 "
        "{%0,%1,%2,%3}, {%4,%5,%6,%7}, {%8,%9}, {%0,%1,%2,%3};"
        : "+f"(c[0]), "+f"(c[1]), "+f"(c[2]), "+f"(c[3])
        : "r"(a0), "r"(a1), "r"(a2), "r"(a3), "r"(b0), "r"(b1));
}

// ---------------------------------------------------------------------------
// Kernel A: Wh = x @ W via tf32 mma.sync. Block = 64 rows x 64 cols, K=512.
// Writes g_Wh (natural layout, fp32) and g_WhB (tf32, column-permuted).
// ---------------------------------------------------------------------------
#define XS_STR 36
#define WS_STR 72
__global__ __launch_bounds__(256) void wh_kernel(const float* __restrict__ x,
                                                 const float* __restrict__ W) {
    __shared__ __align__(16) float xs[2][64 * XS_STR];
    __shared__ __align__(16) float ws[2][32 * WS_STR];

    const int tid  = threadIdx.x;
    const int w    = tid >> 5, lane = tid & 31;
    const int wr   = w & 3,    wc   = w >> 2;
    const int g    = lane >> 2, tig = lane & 3;
    const int r0   = blockIdx.x * 64;
    const int r0l  = wr * 16 + g;
    const int r1l  = r0l + 8;

    const uint32_t xs0 = smem_u32(xs);
    const uint32_t ws0 = smem_u32(ws);

    auto prefetch = [&](int s) {
        if (s < 16) {
            int b = s & 1;
            int k0 = s * 32;
            #pragma unroll
            for (int c = tid; c < 512; c += 256) {     // x: 64 rows x 32 k
                int r = c >> 3, q = c & 7;
                cp_async16(xs0 + (b * 64 * XS_STR + r * XS_STR) * 4 + q * 16,
                           x + (size_t)(r0 + r) * F_IN + k0 + q * 4);
            }
            #pragma unroll
            for (int c = tid; c < 512; c += 256) {     // W: 32 k x 64 f
                int r = c >> 4, q = c & 15;
                cp_async16(ws0 + (b * 32 * WS_STR + r * WS_STR) * 4 + q * 16,
                           W + (size_t)(k0 + r) * F_OUT + q * 4);
            }
        }
        cp_commit();
    };

    float acc[4][4] = {};
    prefetch(0);

    for (int s = 0; s < 16; ++s) {
        prefetch(s + 1);
        cp_wait1();
        __syncthreads();

        const float* xp = &xs[s & 1][0];
        const float* wp = &ws[s & 1][0];

        #pragma unroll
        for (int kc = 0; kc < 4; ++kc) {
            uint32_t a0 = to_tf32(xp[r0l * XS_STR + kc * 8 + tig]);
            uint32_t a1 = to_tf32(xp[r1l * XS_STR + kc * 8 + tig]);
            uint32_t a2 = to_tf32(xp[r0l * XS_STR + kc * 8 + tig + 4]);
            uint32_t a3 = to_tf32(xp[r1l * XS_STR + kc * 8 + tig + 4]);
            #pragma unroll
            for (int n = 0; n < 4; ++n) {
                int f = wc * 32 + n * 8 + g;
                uint32_t b0 = to_tf32(wp[(kc * 8 + tig)     * WS_STR + f]);
                uint32_t b1 = to_tf32(wp[(kc * 8 + tig + 4) * WS_STR + f]);
                mma_tf32(acc[n], a0, a1, a2, a3, b0, b1);
            }
        }
        __syncthreads();
    }

    #pragma unroll
    for (int n = 0; n < 4; ++n) {
        int f = wc * 32 + n * 8 + tig * 2;   // original columns f, f+1
        size_t o0 = (size_t)(r0 + r0l) * F_OUT + f;
        size_t o1 = (size_t)(r0 + r1l) * F_OUT + f;
        *(float2*)&g_Wh[o0] = make_float2(acc[n][0], acc[n][1]);
        *(float2*)&g_Wh[o1] = make_float2(acc[n][2], acc[n][3]);
        // permuted: f has nblk=wc*4+n, gg=tig*2 -> p = wc*32 + tig*8 + n
        // f+1: gg=tig*2+1 -> p+4
        int p0 = wc * 32 + tig * 8 + n;
        g_WhB[(size_t)(r0 + r0l) * F_OUT + p0]     = __uint_as_float(to_tf32(acc[n][0]));
        g_WhB[(size_t)(r0 + r0l) * F_OUT + p0 + 4] = __uint_as_float(to_tf32(acc[n][1]));
        g_WhB[(size_t)(r0 + r1l) * F_OUT + p0]     = __uint_as_float(to_tf32(acc[n][2]));
        g_WhB[(size_t)(r0 + r1l) * F_OUT + p0 + 4] = __uint_as_float(to_tf32(acc[n][3]));
    }
}

// ---------------------------------------------------------------------------
// Kernel B: s1 = Wh @ a1, s2 = Wh @ a2
// ---------------------------------------------------------------------------
__global__ __launch_bounds__(256) void s_kernel(const float* __restrict__ A) {
    const int row  = blockIdx.x * 8 + (threadIdx.x >> 5);
    const int lane = threadIdx.x & 31;
    float w0 = g_Wh[row * F_OUT + lane];
    float w1 = g_Wh[row * F_OUT + lane + 32];
    float v1 = w0 * A[lane]         + w1 * A[lane + 32];
    float v2 = w0 * A[F_OUT + lane] + w1 * A[F_OUT + lane + 32];
    #pragma unroll
    for (int off = 16; off; off >>= 1) {
        v1 += __shfl_xor_sync(0xFFFFFFFFu, v1, off);
        v2 += __shfl_xor_sync(0xFFFFFFFFu, v2, off);
    }
    if (lane == 0) { g_s1[row] = v1; g_s2[row] = v2; }
}

// ---------------------------------------------------------------------------
// Kernel B2: g_s2max = max(g_s2)
// ---------------------------------------------------------------------------
__global__ __launch_bounds__(1024) void s2max_kernel() {
    __shared__ float sm[32];
    const int tid = threadIdx.x;
    float m = -INFINITY;
    for (int i = tid; i < N_NODES; i += 1024) m = fmaxf(m, g_s2[i]);
    #pragma unroll
    for (int off = 16; off; off >>= 1)
        m = fmaxf(m, __shfl_xor_sync(0xFFFFFFFFu, m, off));
    if ((tid & 31) == 0) sm[tid >> 5] = m;
    __syncthreads();
    if (tid < 32) {
        m = sm[tid];
        #pragma unroll
        for (int off = 16; off; off >>= 1)
            m = fmaxf(m, __shfl_xor_sync(0xFFFFFFFFu, m, off));
        if (tid == 0) g_s2max = m;
    }
}

// ---------------------------------------------------------------------------
// Kernel C: fused attention via mma.sync tf32 (m16n8k8).
// grid = 128 i-blocks x 8 j-slices = 1024 blocks, 3 blocks/SM.
// 8 warps = 4 row-tiles (wr) x 2 J-HALVES (jh). Each warp: 16 rows x 16 j x
// 64 f  -> exp work is NOT duplicated. j-half partials merged in epilogue.
// ---------------------------------------------------------------------------
__global__ __launch_bounds__(256, 3) void attn_kernel(const int* __restrict__ adj) {
    extern __shared__ __align__(1024) char smem[];
    const int tid  = threadIdx.x;
    const int w    = tid >> 5, lane = tid & 31;
    const int wr   = w & 3,    jh   = w >> 2;
    const int g    = lane >> 2, tig = lane & 3;
    const int i0   = (blockIdx.x >> 3) * ROWS_B;
    const int qh   = blockIdx.x & 7;
    const int j0b  = qh * JQ;
    const int r0l  = wr * 16 + g;
    const int r1l  = r0l + 8;

    const uint32_t sb = smem_u32(smem);

    auto prefetch = [&](int t) {
        if (t < TILES_B) {
            uint32_t base = sb + (t & 3) * STAGE;
            const int j0 = j0b + t * TJ;
            #pragma unroll
            for (int c = tid; c < 512; c += 256) {       // adj 64x32 ints
                int r = c >> 3, q = c & 7;
                cp_async16(base + r * ADJ_STRIDE + q * 16,
                           adj + (size_t)(i0 + r) * N_NODES + j0 + q * 4);
            }
            #pragma unroll
            for (int c = tid; c < 512; c += 256) {       // WhB 32x64 floats
                int r = c >> 4, q = c & 15;
                cp_async16(base + WH_OFF + r * WH_STRIDE + q * 16,
                           g_WhB + (j0 + r) * F_OUT + q * 4);
            }
            if (tid < 8)                                 // s2 32 floats
                cp_async16(base + S2_OFF + tid * 16, g_s2 + j0 + tid * 4);
        }
        cp_commit();
    };

    const float s1_0 = g_s1[i0 + r0l];
    const float s1_1 = g_s1[i0 + r1l];
    const float s2m  = g_s2max;
    const float m0 = fmaxf(s1_0 + s2m, ALPHA * (s1_0 + s2m));
    const float m1 = fmaxf(s1_1 + s2m, ALPHA * (s1_1 + s2m));

    float acc[8][4] = {};                 // full 64 f per warp
    float sum0 = 0.f, sum1 = 0.f;

    prefetch(0); prefetch(1); prefetch(2);

    for (int t = 0; t < TILES_B; ++t) {
        cp_wait2();
        __syncthreads();
        prefetch(t + 3);     // refills slot (t-1)&3; reads of t-1 done pre-barrier

        const char*  base = smem + (t & 3) * STAGE;
        const float* s2p  = (const float*)(base + S2_OFF);
        const float* whp  = (const float*)(base + WH_OFF);

        // A fragments for this warp's 16-j half: 8 weights (2 rows x 4 j)
        uint32_t aw[2][4];
        #pragma unroll
        for (int kc = 0; kc < 2; ++kc) {
            #pragma unroll
            for (int h = 0; h < 2; ++h) {
                int j = jh * 16 + kc * 8 + tig + 4 * h;
                float s2v = s2p[j];
                int a0 = *(const int*)(base + r0l * ADJ_STRIDE + j * 4);
                int a1 = *(const int*)(base + r1l * ADJ_STRIDE + j * 4);
                float t0 = s1_0 + s2v;
                float t1 = s1_1 + s2v;
                float e0 = fmaxf(t0, ALPHA * t0);
                float e1 = fmaxf(t1, ALPHA * t1);
                float w0 = (a0 > 0) ? __expf(e0 - m0) : 0.f;
                float w1 = (a1 > 0) ? __expf(e1 - m1) : 0.f;
                sum0 += w0; sum1 += w1;
                aw[kc][2 * h]     = to_tf32(w0);
                aw[kc][2 * h + 1] = to_tf32(w1);
            }
        }

        // MMA over this warp's 16 j (2 k-chunks), full 64 f.
        // B layout per row: thread's n=0..3 at floats g*4.., n=4..7 at 32+g*4..
        #pragma unroll
        for (int kc = 0; kc < 2; ++kc) {
            int jr0 = jh * 16 + kc * 8 + tig;       // k = tig
            int jr1 = jr0 + 4;                       // k = tig+4
            float4 bl0 = *(const float4*)&whp[jr0 * 72 + g * 4];        // b0, n0..3
            float4 bh0 = *(const float4*)&whp[jr0 * 72 + 32 + g * 4];   // b0, n4..7
            float4 bl1 = *(const float4*)&whp[jr1 * 72 + g * 4];        // b1, n0..3
            float4 bh1 = *(const float4*)&whp[jr1 * 72 + 32 + g * 4];   // b1, n4..7
            uint32_t a0 = aw[kc][0], a1 = aw[kc][1];
            uint32_t a2 = aw[kc][2], a3 = aw[kc][3];
            mma_tf32(acc[0], a0, a1, a2, a3, __float_as_uint(bl0.x), __float_as_uint(bl1.x));
            mma_tf32(acc[1], a0, a1, a2, a3, __float_as_uint(bl0.y), __float_as_uint(bl1.y));
            mma_tf32(acc[2], a0, a1, a2, a3, __float_as_uint(bl0.z), __float_as_uint(bl1.z));
            mma_tf32(acc[3], a0, a1, a2, a3, __float_as_uint(bl0.w), __float_as_uint(bl1.w));
            mma_tf32(acc[4], a0, a1, a2, a3, __float_as_uint(bh0.x), __float_as_uint(bh1.x));
            mma_tf32(acc[5], a0, a1, a2, a3, __float_as_uint(bh0.y), __float_as_uint(bh1.y));
            mma_tf32(acc[6], a0, a1, a2, a3, __float_as_uint(bh0.z), __float_as_uint(bh1.z));
            mma_tf32(acc[7], a0, a1, a2, a3, __float_as_uint(bh0.w), __float_as_uint(bh1.w));
        }
    }

    // ---- epilogue: merge the two j-half partials -------------------------
    __syncthreads();                       // all tiles done; stage smem free
    float* eS    = (float*)smem;           // 64 x 66 floats (16.9 KB)
    float* lsumS = (float*)(smem + 64 * 66 * 4);  // 2 x 64 floats

    sum0 += __shfl_xor_sync(0xFFFFFFFFu, sum0, 1);
    sum0 += __shfl_xor_sync(0xFFFFFFFFu, sum0, 2);
    sum1 += __shfl_xor_sync(0xFFFFFFFFu, sum1, 1);
    sum1 += __shfl_xor_sync(0xFFFFFFFFu, sum1, 2);
    if (tig == 0) {
        lsumS[jh * 64 + r0l] = sum0;
        lsumS[jh * 64 + r1l] = sum1;
    }

    if (jh == 0) {
        #pragma unroll
        for (int n = 0; n < 8; ++n) {
            *(float2*)&eS[r0l * 66 + n * 8 + tig * 2] = make_float2(acc[n][0], acc[n][1]);
            *(float2*)&eS[r1l * 66 + n * 8 + tig * 2] = make_float2(acc[n][2], acc[n][3]);
        }
    }
    __syncthreads();
    if (jh == 1) {
        #pragma unroll
        for (int n = 0; n < 8; ++n) {
            int f = n * 8 + tig * 2;
            float2 p0 = *(const float2*)&eS[r0l * 66 + f];
            float2 p1 = *(const float2*)&eS[r1l * 66 + f];
            *(float2*)&g_part[qh][(size_t)(i0 + r0l) * F_OUT + f] =
                make_float2(acc[n][0] + p0.x, acc[n][1] + p0.y);
            *(float2*)&g_part[qh][(size_t)(i0 + r1l) * F_OUT + f] =
                make_float2(acc[n][2] + p1.x, acc[n][3] + p1.y);
        }
        if (tig == 0) {
            g_lpart[qh][i0 + r0l] = lsumS[r0l] + lsumS[64 + r0l];
            g_lpart[qh][i0 + r1l] = lsumS[r1l] + lsumS[64 + r1l];
        }
    }
}

// ---------------------------------------------------------------------------
// Kernel D: out = (sum_q part_q) / (sum_q l_q) + bias
// ---------------------------------------------------------------------------
__global__ __launch_bounds__(256) void combine_kernel(const float* __restrict__ bias,
                                                      float* __restrict__ out) {
    int idx = blockIdx.x * 256 + threadIdx.x;    // 8192*16 float4 slots
    int i  = idx >> 4;
    int fq = idx & 15;
    size_t off = (size_t)i * F_OUT + fq * 4;

    float4 p = *(const float4*)&g_part[0][off];
    float  l = g_lpart[0][i];
    #pragma unroll
    for (int q = 1; q < JSPLIT; ++q) {
        float4 pq = *(const float4*)&g_part[q][off];
        p.x += pq.x; p.y += pq.y; p.z += pq.z; p.w += pq.w;
        l += g_lpart[q][i];
    }
    float inv = 1.0f / l;
    float4 bz = *(const float4*)&bias[fq * 4];
    float4 r;
    r.x = p.x * inv + bz.x;
    r.y = p.y * inv + bz.y;
    r.z = p.z * inv + bz.z;
    r.w = p.w * inv + bz.w;
    *(float4*)&out[off] = r;
}

// ---------------------------------------------------------------------------
extern "C" void kernel_launch(void* const* d_in, const int* in_sizes, int n_in,
                              void* d_out, int out_size) {
    const float* x    = (const float*)d_in[0];
    const int*   adj  = (const int*)  d_in[1];
    const float* W    = (const float*)d_in[2];
    const float* bias = (const float*)d_in[3];
    const float* A    = (const float*)d_in[4];
    float*       out  = (float*)d_out;

    cudaFuncSetAttribute(attn_kernel,
                         cudaFuncAttributeMaxDynamicSharedMemorySize, SMEM_SZ);

    wh_kernel   <<<N_NODES / 64, 256>>>(x, W);
    s_kernel    <<<N_NODES / 8,  256>>>(A);
    s2max_kernel<<<1, 1024>>>();
    attn_kernel <<<(N_NODES / ROWS_B) * JSPLIT, 256, SMEM_SZ>>>(adj);
    combine_kernel<<<N_NODES * 16 / 256, 256>>>(bias, out);
}

// round 9
// speedup vs baseline: 1.3801x; 1.0166x over previous
#include <cuda_runtime.h>
#include <math.h>
#include <stdint.h>

#define N_NODES 8192
#define F_IN    512
#define F_OUT   64
#define ALPHA   0.2f

#define TJ      32
#define JSPLIT  8
#define JQ      (N_NODES / JSPLIT)   // 1024
#define TILES_B (JQ / TJ)            // 32 tiles per block
#define ROWS_B  64                   // i-rows per block

// SMEM stage layout (bytes)
#define ADJ_STRIDE 144               // 36 ints per adj row (32 data + pad)
#define WH_STRIDE  288               // 72 floats per Wh row (64 data + pad)
#define WH_OFF     9216              // after 64 adj rows
#define S2_OFF     18432
#define STAGE      18560
#define RING       4
#define SMEM_SZ    (STAGE * RING)    // 74240 (x3 blocks = 222.7KB/SM)

// Scratch (no allocations allowed anywhere)
__device__ float g_Wh [N_NODES * F_OUT];
// tf32-rounded, column-permuted (see wh epilogue)
__device__ float g_WhB[N_NODES * F_OUT];
__device__ float g_s1 [N_NODES];
__device__ float g_s2 [N_NODES];
__device__ float g_s2max;
__device__ float g_part [JSPLIT][N_NODES * F_OUT];
__device__ float g_lpart[JSPLIT][N_NODES];

// ---- helpers ---------------------------------------------------------------
__device__ __forceinline__ uint32_t smem_u32(const void* p) {
    uint32_t r;
    asm("{ .reg .u64 t; cvta.to.shared.u64 t, %1; cvt.u32.u64 %0, t; }"
        : "=r"(r) : "l"(p));
    return r;
}
__device__ __forceinline__ void cp_async16(uint32_t dst, const void* src) {
    asm volatile("cp.async.cg.shared.global [%0], [%1], 16;"
                 :: "r"(dst), "l"(src) : "memory");
}
__device__ __forceinline__ void cp_commit() {
    asm volatile("cp.async.commit_group;" ::: "memory");
}
__device__ __forceinline__ void cp_wait1() {
    asm volatile("cp.async.wait_group 1;" ::: "memory");
}
__device__ __forceinline__ void cp_wait2() {
    asm volatile("cp.async.wait_group 2;" ::: "memory");
}
__device__ __forceinline__ uint32_t to_tf32(float x) {
    uint32_t r;
    asm("cvt.rna.tf32.f32 %0, %1;" : "=r"(r) : "f"(x));
    return r;
}
__device__ __forceinline__ void mma_tf32(float* c, uint32_t a0, uint32_t a1,
                                         uint32_t a2, uint32_t a3,
                                         uint32_t b0, uint32_t b1) {
    asm volatile(
        "mma.sync.aligned.m16n8k8.row.col.f32.tf32.tf32.f32 "
        "{%0,%1,%2,%3}, {%4,%5,%6,%7}, {%8,%9}, {%0,%1,%2,%3};"
        : "+f"(c[0]), "+f"(c[1]), "+f"(c[2]), "+f"(c[3])
        : "r"(a0), "r"(a1), "r"(a2), "r"(a3), "r"(b0), "r"(b1));
}

// ---------------------------------------------------------------------------
// Kernel A: Wh = x @ W via tf32 mma.sync. Block = 64 rows x 64 cols, K=512.
// ---------------------------------------------------------------------------
#define XS_STR 36
#define WS_STR 72
__global__ __launch_bounds__(256) void wh_kernel(const float* __restrict__ x,
                                                 const float* __restrict__ W) {
    __shared__ __align__(16) float xs[2][64 * XS_STR];
    __shared__ __align__(16) float ws[2][32 * WS_STR];

    const int tid  = threadIdx.x;
    const int w    = tid >> 5, lane = tid & 31;
    const int wr   = w & 3,    wc   = w >> 2;
    const int g    = lane >> 2, tig = lane & 3;
    const int r0   = blockIdx.x * 64;
    const int r0l  = wr * 16 + g;
    const int r1l  = r0l + 8;

    const uint32_t xs0 = smem_u32(xs);
    const uint32_t ws0 = smem_u32(ws);

    auto prefetch = [&](int s) {
        if (s < 16) {
            int b = s & 1;
            int k0 = s * 32;
            #pragma unroll
            for (int c = tid; c < 512; c += 256) {     // x: 64 rows x 32 k
                int r = c >> 3, q = c & 7;
                cp_async16(xs0 + (b * 64 * XS_STR + r * XS_STR) * 4 + q * 16,
                           x + (size_t)(r0 + r) * F_IN + k0 + q * 4);
            }
            #pragma unroll
            for (int c = tid; c < 512; c += 256) {     // W: 32 k x 64 f
                int r = c >> 4, q = c & 15;
                cp_async16(ws0 + (b * 32 * WS_STR + r * WS_STR) * 4 + q * 16,
                           W + (size_t)(k0 + r) * F_OUT + q * 4);
            }
        }
        cp_commit();
    };

    float acc[4][4] = {};
    prefetch(0);

    for (int s = 0; s < 16; ++s) {
        prefetch(s + 1);
        cp_wait1();
        __syncthreads();

        const float* xp = &xs[s & 1][0];
        const float* wp = &ws[s & 1][0];

        #pragma unroll
        for (int kc = 0; kc < 4; ++kc) {
            uint32_t a0 = to_tf32(xp[r0l * XS_STR + kc * 8 + tig]);
            uint32_t a1 = to_tf32(xp[r1l * XS_STR + kc * 8 + tig]);
            uint32_t a2 = to_tf32(xp[r0l * XS_STR + kc * 8 + tig + 4]);
            uint32_t a3 = to_tf32(xp[r1l * XS_STR + kc * 8 + tig + 4]);
            #pragma unroll
            for (int n = 0; n < 4; ++n) {
                int f = wc * 32 + n * 8 + g;
                uint32_t b0 = to_tf32(wp[(kc * 8 + tig)     * WS_STR + f]);
                uint32_t b1 = to_tf32(wp[(kc * 8 + tig + 4) * WS_STR + f]);
                mma_tf32(acc[n], a0, a1, a2, a3, b0, b1);
            }
        }
        __syncthreads();
    }

    #pragma unroll
    for (int n = 0; n < 4; ++n) {
        int f = wc * 32 + n * 8 + tig * 2;   // original columns f, f+1
        size_t o0 = (size_t)(r0 + r0l) * F_OUT + f;
        size_t o1 = (size_t)(r0 + r1l) * F_OUT + f;
        *(float2*)&g_Wh[o0] = make_float2(acc[n][0], acc[n][1]);
        *(float2*)&g_Wh[o1] = make_float2(acc[n][2], acc[n][3]);
        int p0 = wc * 32 + tig * 8 + n;
        g_WhB[(size_t)(r0 + r0l) * F_OUT + p0]     = __uint_as_float(to_tf32(acc[n][0]));
        g_WhB[(size_t)(r0 + r0l) * F_OUT + p0 + 4] = __uint_as_float(to_tf32(acc[n][1]));
        g_WhB[(size_t)(r0 + r1l) * F_OUT + p0]     = __uint_as_float(to_tf32(acc[n][2]));
        g_WhB[(size_t)(r0 + r1l) * F_OUT + p0 + 4] = __uint_as_float(to_tf32(acc[n][3]));
    }
}

// ---------------------------------------------------------------------------
// Kernel B: s1 = Wh @ a1, s2 = Wh @ a2
// ---------------------------------------------------------------------------
__global__ __launch_bounds__(256) void s_kernel(const float* __restrict__ A) {
    const int row  = blockIdx.x * 8 + (threadIdx.x >> 5);
    const int lane = threadIdx.x & 31;
    float w0 = g_Wh[row * F_OUT + lane];
    float w1 = g_Wh[row * F_OUT + lane + 32];
    float v1 = w0 * A[lane]         + w1 * A[lane + 32];
    float v2 = w0 * A[F_OUT + lane] + w1 * A[F_OUT + lane + 32];
    #pragma unroll
    for (int off = 16; off; off >>= 1) {
        v1 += __shfl_xor_sync(0xFFFFFFFFu, v1, off);
        v2 += __shfl_xor_sync(0xFFFFFFFFu, v2, off);
    }
    if (lane == 0) { g_s1[row] = v1; g_s2[row] = v2; }
}

// ---------------------------------------------------------------------------
// Kernel B2: g_s2max = max(g_s2)
// ---------------------------------------------------------------------------
__global__ __launch_bounds__(1024) void s2max_kernel() {
    __shared__ float sm[32];
    const int tid = threadIdx.x;
    float m = -INFINITY;
    for (int i = tid; i < N_NODES; i += 1024) m = fmaxf(m, g_s2[i]);
    #pragma unroll
    for (int off = 16; off; off >>= 1)
        m = fmaxf(m, __shfl_xor_sync(0xFFFFFFFFu, m, off));
    if ((tid & 31) == 0) sm[tid >> 5] = m;
    __syncthreads();
    if (tid < 32) {
        m = sm[tid];
        #pragma unroll
        for (int off = 16; off; off >>= 1)
            m = fmaxf(m, __shfl_xor_sync(0xFFFFFFFFu, m, off));
        if (tid == 0) g_s2max = m;
    }
}

// ---------------------------------------------------------------------------
// Kernel C: fused attention via mma.sync tf32 (m16n8k8).
// grid = 128 i-blocks x 8 j-slices = 1024 blocks, 3 blocks/SM.
// 8 warps = 4 row-tiles (wr) x 2 j-halves (jh); no duplicated exp work.
// Tile loop unrolled x4: ring-slot smem addresses are loop-invariant.
// ---------------------------------------------------------------------------
__global__ __launch_bounds__(256, 3) void attn_kernel(const int* __restrict__ adj) {
    extern __shared__ __align__(1024) char smem[];
    const int tid  = threadIdx.x;
    const int w    = tid >> 5, lane = tid & 31;
    const int wr   = w & 3,    jh   = w >> 2;
    const int g    = lane >> 2, tig = lane & 3;
    const int i0   = (blockIdx.x >> 3) * ROWS_B;
    const int qh   = blockIdx.x & 7;
    const int j0b  = qh * JQ;
    const int r0l  = wr * 16 + g;
    const int r1l  = r0l + 8;

    const uint32_t sb = smem_u32(smem);

    // per-thread invariant offsets (bytes)
    const int pr  = tid >> 3, pq8 = tid & 7;      // adj prefetch row/quad
    const int wr_ = tid >> 4, wq  = tid & 15;     // WhB prefetch row/quad
    const uint32_t adj_dst0 = sb + pr * ADJ_STRIDE + pq8 * 16;
    const uint32_t adj_dst1 = adj_dst0 + 32 * ADJ_STRIDE;
    const uint32_t wh_dst0  = sb + WH_OFF + wr_ * WH_STRIDE + wq * 16;
    const uint32_t wh_dst1  = wh_dst0 + 16 * WH_STRIDE;
    const int      a_row0   = r0l * ADJ_STRIDE;
    const int      a_row1   = r1l * ADJ_STRIDE;

    // incrementing global sources
    const int* adj_src0 = adj + (size_t)(i0 + pr)      * N_NODES + j0b + pq8 * 4;
    const int* adj_src1 = adj + (size_t)(i0 + pr + 32) * N_NODES + j0b + pq8 * 4;
    const float* wh_src0 = g_WhB + (size_t)(j0b + wr_)      * F_OUT + wq * 4;
    const float* wh_src1 = g_WhB + (size_t)(j0b + wr_ + 16) * F_OUT + wq * 4;
    const float* s2_src  = g_s2 + j0b + (tid & 7) * 4;

    auto prefetch = [&](int t) {
        if (t < TILES_B) {
            uint32_t base = (uint32_t)((t & 3) * STAGE);
            int joff = t * TJ;
            cp_async16(adj_dst0 + base, adj_src0 + joff);
            cp_async16(adj_dst1 + base, adj_src1 + joff);
            cp_async16(wh_dst0 + base, wh_src0 + (size_t)joff * F_OUT);
            cp_async16(wh_dst1 + base, wh_src1 + (size_t)joff * F_OUT);
            if (tid < 8)
                cp_async16(sb + S2_OFF + base + tid * 16, s2_src + joff);
        }
        cp_commit();
    };

    const float s1_0 = g_s1[i0 + r0l];
    const float s1_1 = g_s1[i0 + r1l];
    const float s2m  = g_s2max;
    const float m0 = fmaxf(s1_0 + s2m, ALPHA * (s1_0 + s2m));
    const float m1 = fmaxf(s1_1 + s2m, ALPHA * (s1_1 + s2m));

    float acc[8][4] = {};
    float sum0 = 0.f, sum1 = 0.f;

    prefetch(0); prefetch(1); prefetch(2);

    #pragma unroll 4
    for (int t = 0; t < TILES_B; ++t) {
        cp_wait2();
        __syncthreads();
        prefetch(t + 3);     // refills slot (t-1)&3; reads of t-1 done pre-barrier

        const char*  base = smem + (t & 3) * STAGE;
        const float* s2p  = (const float*)(base + S2_OFF);
        const float* whp  = (const float*)(base + WH_OFF);

        // A fragments for this warp's 16-j half: 8 weights (2 rows x 4 j)
        uint32_t aw[2][4];
        #pragma unroll
        for (int kc = 0; kc < 2; ++kc) {
            #pragma unroll
            for (int h = 0; h < 2; ++h) {
                int j = jh * 16 + kc * 8 + tig + 4 * h;
                float s2v = s2p[j];
                int a0 = *(const int*)(base + a_row0 + j * 4);
                int a1 = *(const int*)(base + a_row1 + j * 4);
                float t0 = s1_0 + s2v;
                float t1 = s1_1 + s2v;
                float e0 = fmaxf(t0, ALPHA * t0);
                float e1 = fmaxf(t1, ALPHA * t1);
                float w0 = (a0 > 0) ? __expf(e0 - m0) : 0.f;
                float w1 = (a1 > 0) ? __expf(e1 - m1) : 0.f;
                sum0 += w0; sum1 += w1;
                aw[kc][2 * h]     = to_tf32(w0);
                aw[kc][2 * h + 1] = to_tf32(w1);
            }
        }

        // MMA over this warp's 16 j (2 k-chunks), full 64 f.
        #pragma unroll
        for (int kc = 0; kc < 2; ++kc) {
            int jr0 = jh * 16 + kc * 8 + tig;
            int jr1 = jr0 + 4;
            float4 bl0 = *(const float4*)&whp[jr0 * 72 + g * 4];
            float4 bh0 = *(const float4*)&whp[jr0 * 72 + 32 + g * 4];
            float4 bl1 = *(const float4*)&whp[jr1 * 72 + g * 4];
            float4 bh1 = *(const float4*)&whp[jr1 * 72 + 32 + g * 4];
            uint32_t a0 = aw[kc][0], a1 = aw[kc][1];
            uint32_t a2 = aw[kc][2], a3 = aw[kc][3];
            mma_tf32(acc[0], a0, a1, a2, a3, __float_as_uint(bl0.x), __float_as_uint(bl1.x));
            mma_tf32(acc[1], a0, a1, a2, a3, __float_as_uint(bl0.y), __float_as_uint(bl1.y));
            mma_tf32(acc[2], a0, a1, a2, a3, __float_as_uint(bl0.z), __float_as_uint(bl1.z));
            mma_tf32(acc[3], a0, a1, a2, a3, __float_as_uint(bl0.w), __float_as_uint(bl1.w));
            mma_tf32(acc[4], a0, a1, a2, a3, __float_as_uint(bh0.x), __float_as_uint(bh1.x));
            mma_tf32(acc[5], a0, a1, a2, a3, __float_as_uint(bh0.y), __float_as_uint(bh1.y));
            mma_tf32(acc[6], a0, a1, a2, a3, __float_as_uint(bh0.z), __float_as_uint(bh1.z));
            mma_tf32(acc[7], a0, a1, a2, a3, __float_as_uint(bh0.w), __float_as_uint(bh1.w));
        }
    }

    // ---- epilogue: merge the two j-half partials -------------------------
    __syncthreads();                       // all tiles done; stage smem free
    float* eS    = (float*)smem;           // 64 x 66 floats (16.9 KB)
    float* lsumS = (float*)(smem + 64 * 66 * 4);  // 2 x 64 floats

    sum0 += __shfl_xor_sync(0xFFFFFFFFu, sum0, 1);
    sum0 += __shfl_xor_sync(0xFFFFFFFFu, sum0, 2);
    sum1 += __shfl_xor_sync(0xFFFFFFFFu, sum1, 1);
    sum1 += __shfl_xor_sync(0xFFFFFFFFu, sum1, 2);
    if (tig == 0) {
        lsumS[jh * 64 + r0l] = sum0;
        lsumS[jh * 64 + r1l] = sum1;
    }

    if (jh == 0) {
        #pragma unroll
        for (int n = 0; n < 8; ++n) {
            *(float2*)&eS[r0l * 66 + n * 8 + tig * 2] = make_float2(acc[n][0], acc[n][1]);
            *(float2*)&eS[r1l * 66 + n * 8 + tig * 2] = make_float2(acc[n][2], acc[n][3]);
        }
    }
    __syncthreads();
    if (jh == 1) {
        #pragma unroll
        for (int n = 0; n < 8; ++n) {
            int f = n * 8 + tig * 2;
            float2 p0 = *(const float2*)&eS[r0l * 66 + f];
            float2 p1 = *(const float2*)&eS[r1l * 66 + f];
            *(float2*)&g_part[qh][(size_t)(i0 + r0l) * F_OUT + f] =
                make_float2(acc[n][0] + p0.x, acc[n][1] + p0.y);
            *(float2*)&g_part[qh][(size_t)(i0 + r1l) * F_OUT + f] =
                make_float2(acc[n][2] + p1.x, acc[n][3] + p1.y);
        }
        if (tig == 0) {
            g_lpart[qh][i0 + r0l] = lsumS[r0l] + lsumS[64 + r0l];
            g_lpart[qh][i0 + r1l] = lsumS[r1l] + lsumS[64 + r1l];
        }
    }
}

// ---------------------------------------------------------------------------
// Kernel D: out = (sum_q part_q) / (sum_q l_q) + bias
// ---------------------------------------------------------------------------
__global__ __launch_bounds__(256) void combine_kernel(const float* __restrict__ bias,
                                                      float* __restrict__ out) {
    int idx = blockIdx.x * 256 + threadIdx.x;    // 8192*16 float4 slots
    int i  = idx >> 4;
    int fq = idx & 15;
    size_t off = (size_t)i * F_OUT + fq * 4;

    float4 p = *(const float4*)&g_part[0][off];
    float  l = g_lpart[0][i];
    #pragma unroll
    for (int q = 1; q < JSPLIT; ++q) {
        float4 pq = *(const float4*)&g_part[q][off];
        p.x += pq.x; p.y += pq.y; p.z += pq.z; p.w += pq.w;
        l += g_lpart[q][i];
    }
    float inv = 1.0f / l;
    float4 bz = *(const float4*)&bias[fq * 4];
    float4 r;
    r.x = p.x * inv + bz.x;
    r.y = p.y * inv + bz.y;
    r.z = p.z * inv + bz.z;
    r.w = p.w * inv + bz.w;
    *(float4*)&out[off] = r;
}

// ---------------------------------------------------------------------------
extern "C" void kernel_launch(void* const* d_in, const int* in_sizes, int n_in,
                              void* d_out, int out_size) {
    const float* x    = (const float*)d_in[0];
    const int*   adj  = (const int*)  d_in[1];
    const float* W    = (const float*)d_in[2];
    const float* bias = (const float*)d_in[3];
    const float* A    = (const float*)d_in[4];
    float*       out  = (float*)d_out;

    cudaFuncSetAttribute(attn_kernel,
                         cudaFuncAttributeMaxDynamicSharedMemorySize, SMEM_SZ);

    wh_kernel   <<<N_NODES / 64, 256>>>(x, W);
    s_kernel    <<<N_NODES / 8,  256>>>(A);
    s2max_kernel<<<1, 1024>>>();
    attn_kernel <<<(N_NODES / ROWS_B) * JSPLIT, 256, SMEM_SZ>>>(adj);
    combine_kernel<<<N_NODES * 16 / 256, 256>>>(bias, out);
}